// round 16
// baseline (speedup 1.0000x reference)
#include <cuda_runtime.h>
#include <math.h>

// Problem constants (fixed by the dataset instance)
#define BATCH   8
#define NP      4096
#define FDIM    512
#define H1DIM   256
#define H2DIM   128
#define DDIM    6

#define FSCORE_W 0.1f
#define TASK_W   1.0f
#define DOMAIN_W 0.1f
#define INV_C    5000.0f       // 1/(2*sigma^2)

// Chamfer tiling
#define TPB     256
#define PPT     4
#define QTILE   (TPB*PPT)      // 1024 queries per block
#define QB      (NP/QTILE)     // 4
#define KSPLIT  8
#define KCHUNK  (NP/KSPLIT)    // 512 keys per block
#define KTILE   256            // keys per shared tile
#define NTILES  (KCHUNK/KTILE) // 2

#define NGROUPS (2*BATCH*QB)           // 64 chamfer groups
#define NARRIVE (NGROUPS + BATCH)      // + 8 domain blocks = 72

// Scratch (device globals; data slots written unconditionally each launch).
__device__ float g_pmin[2][BATCH][KSPLIT][NP];  // per-split partial mins
__device__ float g_r3[2][BATCH][QB][2];         // per-group (sum_d, sum_exp)
__device__ float g_dom[BATCH];
__device__ int   g_ctr_q[2][BATCH][QB];         // zero-init; self-resetting
__device__ int   g_ctr = 0;                     // zero-init; self-resetting

// ---------------- f32x2 helpers (sm_100+ packed fp32) ----------------
__device__ __forceinline__ unsigned long long pack2(float lo, float hi) {
    unsigned long long r;
    asm("mov.b64 %0, {%1, %2};" : "=l"(r) : "f"(lo), "f"(hi));
    return r;
}
__device__ __forceinline__ unsigned long long fma2(unsigned long long a,
                                                   unsigned long long b,
                                                   unsigned long long c) {
    unsigned long long r;
    asm("fma.rn.f32x2 %0, %1, %2, %3;" : "=l"(r) : "l"(a), "l"(b), "l"(c));
    return r;
}
__device__ __forceinline__ float2 unpack2(unsigned long long v) {
    float2 f;
    asm("mov.b64 {%0, %1}, %2;" : "=f"(f.x), "=f"(f.y) : "l"(v));
    return f;
}

// Shared: double-buffered packed key tiles (chamfer path).
// Layout per buffer (aliased as ulonglong2[KTILE/2]):
//   sA: pair j -> {-2x pair} at floats [4j,4j+1], {-2y pair} at [4j+2,4j+3]
//   sB: pair j -> {-2z pair},            {|k|^2 pair}
__shared__ float sA[2][KTILE * 2];
__shared__ float sB[2][KTILE * 2];
// Shared: domain path (distinct blocks; coexists in static smem).
__shared__ float xs[FDIM];
__shared__ float h1[H1DIM];
__shared__ float h2[H2DIM];
__shared__ float lg[DDIM];
// Shared: epilogue flags/reductions.
__shared__ float red2[8][2];
__shared__ int   sh_last, sh_final;

// Final combine (32 threads of whichever block arrives last).
__device__ __forceinline__ void final_combine(
    const float* __restrict__ dsw, float* __restrict__ out, int t)
{
    float sA_ = 0.f, sEA = 0.f, sB_ = 0.f, sEB = 0.f;
    float dwc = 0.f, domc = 0.f;
    if (t < BATCH) {
        #pragma unroll
        for (int qb = 0; qb < QB; qb++) {
            sA_ += g_r3[0][t][qb][0];
            sEA += g_r3[0][t][qb][1];
            sB_ += g_r3[1][t][qb][0];
            sEB += g_r3[1][t][qb][1];
        }
        const float invN = 1.0f / (float)NP;
        float ch_i = sA_ * invN + sB_ * invN;
        float p_i  = sEA * invN;
        float r_i  = sEB * invN;
        float f_i  = 2.0f * p_i * r_i / (p_i + r_i + 1e-8f);
        float loss_i = ch_i + FSCORE_W * (1.0f - f_i);
        dwc  = dsw[t] * loss_i;
        domc = g_dom[t];
    }
    #pragma unroll
    for (int s = 16; s > 0; s >>= 1) {
        sA_  += __shfl_xor_sync(0xffffffffu, sA_,  s);
        sEA  += __shfl_xor_sync(0xffffffffu, sEA,  s);
        sB_  += __shfl_xor_sync(0xffffffffu, sB_,  s);
        sEB  += __shfl_xor_sync(0xffffffffu, sEB,  s);
        dwc  += __shfl_xor_sync(0xffffffffu, dwc,  s);
        domc += __shfl_xor_sync(0xffffffffu, domc, s);
    }
    if (t == 0) {
        const float invBN = 1.0f / (float)(BATCH * NP);
        float chamfer = sA_ * invBN + sB_ * invBN;
        float prec = sEA * invBN;
        float rec  = sEB * invBN;
        float fscore = 2.0f * prec * rec / (prec + rec + 1e-8f);
        float task = chamfer + FSCORE_W * (1.0f - fscore);
        out[0] = TASK_W * task + DOMAIN_W * (domc / (float)BATCH)
               + (dwc / (float)BATCH);
    }
}

// Arrive on the global counter; last arriver (of NARRIVE) runs the combine.
__device__ __forceinline__ void global_arrive(
    const float* __restrict__ dsw, float* __restrict__ out, int tid)
{
    __threadfence();
    if (tid == 0) {
        int old = atomicAdd(&g_ctr, 1);
        sh_final = (old == NARRIVE - 1) ? 1 : 0;
        if (sh_final) atomicExch(&g_ctr, 0);   // reset for graph replay
    }
    __syncthreads();
    if (sh_final && tid < 32) final_combine(dsw, out, tid);
}

// Domain MLP with 256 threads (one output per thread in layer 1).
__device__ __forceinline__ void domain_block(
    int b, int tid,
    const float* __restrict__ X,
    const float* __restrict__ W1, const float* __restrict__ b1,
    const float* __restrict__ W2, const float* __restrict__ b2,
    const float* __restrict__ W3, const float* __restrict__ b3,
    const int* __restrict__ labels)
{
    for (int i = tid; i < FDIM; i += TPB) xs[i] = X[b * FDIM + i];
    __syncthreads();
    {   // layer 1: 256 threads x 1 output
        float a = b1[tid];
        #pragma unroll 8
        for (int f = 0; f < FDIM; f++)
            a = fmaf(xs[f], W1[f * H1DIM + tid], a);
        h1[tid] = fmaxf(a, 0.0f);
    }
    __syncthreads();
    if (tid < H2DIM) {   // layer 2
        float a = b2[tid];
        #pragma unroll 8
        for (int k = 0; k < H1DIM; k++)
            a = fmaf(h1[k], W2[k * H2DIM + tid], a);
        h2[tid] = fmaxf(a, 0.0f);
    }
    __syncthreads();
    if (tid < DDIM) {
        float a = b3[tid];
        #pragma unroll 8
        for (int k = 0; k < H2DIM; k++)
            a = fmaf(h2[k], W3[k * DDIM + tid], a);
        lg[tid] = a;
    }
    __syncthreads();
    if (tid == 0) {
        float mx = lg[0];
        for (int d = 1; d < DDIM; d++) mx = fmaxf(mx, lg[d]);
        float se = 0.f;
        for (int d = 0; d < DDIM; d++) se += expf(lg[d] - mx);
        g_dom[b] = (mx + logf(se)) - lg[labels[b]];
    }
    __syncthreads();
}

// Single launch: chamfer (y<16), domain MLP (y==16, x==0). Reduction and the
// final combine happen in-kernel via completion counters.
__global__ __launch_bounds__(TPB) void main_kernel(
    const float* __restrict__ P, const float* __restrict__ T,
    const float* __restrict__ X,
    const float* __restrict__ W1, const float* __restrict__ b1,
    const float* __restrict__ W2, const float* __restrict__ b2,
    const float* __restrict__ W3, const float* __restrict__ b3,
    const int* __restrict__ labels,
    const float* __restrict__ dsw, float* __restrict__ out)
{
    const int tid = threadIdx.x;
    const int b   = blockIdx.z;

    if (blockIdx.y == 2 * KSPLIT) {
        if (blockIdx.x == 0) {
            domain_block(b, tid, X, W1, b1, W2, b2, W3, b3, labels);
            global_arrive(dsw, out, tid);
        }
        return;
    }

    const int dir   = blockIdx.y & 1;
    const int split = blockIdx.y >> 1;
    const int qb    = blockIdx.x;
    const int k0    = split * KCHUNK;

    const float* Q = dir ? (T + (size_t)b * NP * 3) : (P + (size_t)b * NP * 3);
    const float* K = dir ? (P + (size_t)b * NP * 3) : (T + (size_t)b * NP * 3);

    unsigned long long qxd[PPT], qyd[PPT], qzd[PPT];
    float q2[PPT], emin[PPT];
    #pragma unroll
    for (int p = 0; p < PPT; p++) {
        int q = qb * QTILE + p * TPB + tid;
        float qx = Q[q * 3 + 0];
        float qy = Q[q * 3 + 1];
        float qz = Q[q * 3 + 2];
        qxd[p] = pack2(qx, qx);
        qyd[p] = pack2(qy, qy);
        qzd[p] = pack2(qz, qz);
        q2[p]  = qx * qx + qy * qy + qz * qz;
        emin[p] = 1e30f;
    }

    const int jo = (tid >> 1) * 4 + (tid & 1);   // packed store offset

    // Prologue: tile 0 (one key per thread; TPB == KTILE).
    float kx = K[(k0 + tid) * 3 + 0];
    float ky = K[(k0 + tid) * 3 + 1];
    float kz = K[(k0 + tid) * 3 + 2];
    sA[0][jo]     = -2.0f * kx;
    sA[0][jo + 2] = -2.0f * ky;
    sB[0][jo]     = -2.0f * kz;
    sB[0][jo + 2] = kx * kx + ky * ky + kz * kz;
    __syncthreads();

    for (int t = 0; t < NTILES; t++) {
        const int buf = t & 1;
        if (t + 1 < NTILES) {
            int k = k0 + (t + 1) * KTILE + tid;
            kx = K[k * 3 + 0];
            ky = K[k * 3 + 1];
            kz = K[k * 3 + 2];
        }

        const ulonglong2* pA = (const ulonglong2*)sA[buf];
        const ulonglong2* pB = (const ulonglong2*)sB[buf];
        #pragma unroll 8
        for (int j = 0; j < KTILE / 2; j++) {
            ulonglong2 A = pA[j];   // LDS.128 warp-uniform broadcast
            ulonglong2 B = pB[j];
            #pragma unroll
            for (int p = 0; p < PPT; p++) {
                unsigned long long e = fma2(qxd[p], A.x, B.y);
                e = fma2(qyd[p], A.y, e);
                e = fma2(qzd[p], B.x, e);
                float2 ef = unpack2(e);
                emin[p] = fminf(emin[p], fminf(ef.x, ef.y));
            }
        }

        if (t + 1 < NTILES) {
            const int nbuf = buf ^ 1;
            sA[nbuf][jo]     = -2.0f * kx;
            sA[nbuf][jo + 2] = -2.0f * ky;
            sB[nbuf][jo]     = -2.0f * kz;
            sB[nbuf][jo + 2] = kx * kx + ky * ky + kz * kz;
        }
        __syncthreads();
    }

    #pragma unroll
    for (int p = 0; p < PPT; p++) {
        int q = qb * QTILE + p * TPB + tid;   // coalesced unique store
        g_pmin[dir][b][split][q] = emin[p] + q2[p];
    }

    // ---- group arrive: last of the KSPLIT blocks reduces this q-range ----
    __threadfence();
    if (tid == 0) {
        int old = atomicAdd(&g_ctr_q[dir][b][qb], 1);
        sh_last = (old == KSPLIT - 1) ? 1 : 0;
        if (sh_last) g_ctr_q[dir][b][qb] = 0;   // reset for graph replay
    }
    __syncthreads();
    if (!sh_last) return;

    {
        float sd = 0.f, se = 0.f;
        #pragma unroll
        for (int i = 0; i < PPT; i++) {
            int q = qb * QTILE + i * TPB + tid;   // coalesced across threads
            float m = g_pmin[dir][b][0][q];
            #pragma unroll
            for (int s = 1; s < KSPLIT; s++)
                m = fminf(m, g_pmin[dir][b][s][q]);
            sd += m;
            se += __expf(-m * INV_C);
        }
        #pragma unroll
        for (int s = 16; s > 0; s >>= 1) {
            sd += __shfl_xor_sync(0xffffffffu, sd, s);
            se += __shfl_xor_sync(0xffffffffu, se, s);
        }
        int w = tid >> 5;
        if ((tid & 31) == 0) { red2[w][0] = sd; red2[w][1] = se; }
        __syncthreads();
        if (tid == 0) {
            float a0 = 0.f, a1 = 0.f;
            #pragma unroll
            for (int ww = 0; ww < 8; ww++) { a0 += red2[ww][0]; a1 += red2[ww][1]; }
            g_r3[dir][b][qb][0] = a0;
            g_r3[dir][b][qb][1] = a1;
        }
    }

    global_arrive(dsw, out, tid);
}

extern "C" void kernel_launch(void* const* d_in, const int* in_sizes, int n_in,
                              void* d_out, int out_size)
{
    const float* pred_pc   = (const float*)d_in[0];
    const float* target_pc = (const float*)d_in[1];
    const float* dfeat     = (const float*)d_in[2];
    const float* dsw       = (const float*)d_in[3];
    const float* W1 = (const float*)d_in[4];
    const float* b1 = (const float*)d_in[5];
    const float* W2 = (const float*)d_in[6];
    const float* b2 = (const float*)d_in[7];
    const float* W3 = (const float*)d_in[8];
    const float* b3 = (const float*)d_in[9];
    const int*   labels = (const int*)d_in[10];
    float* out = (float*)d_out;

    // (4, 17, 8): y<16 chamfer split/dir blocks; y==16,x==0 domain blocks.
    dim3 grid(QB, 2 * KSPLIT + 1, BATCH);
    main_kernel<<<grid, TPB>>>(pred_pc, target_pc, dfeat,
                               W1, b1, W2, b2, W3, b3, labels, dsw, out);
}